// round 1
// baseline (speedup 1.0000x reference)
#include <cuda_runtime.h>
#include <math.h>

#define HH 960
#define WW 1280
#define NPIX (HH*WW)
#define HUBER_Bf 0.02f
#define L_RGBf 1e-6f
#define DAMPINGd 0.001

// ---------------- scratch (static device globals; no allocation) ----------------
__device__ float4       g_nrm1[NPIX];   // normal1.xyz + depth1 in .w
__device__ double       g_acc[3][27];   // per-iteration: 21 upper-tri JtWJ + 6 JtR
__device__ float        g_pose[16];     // current 4x4 pose, row-major
__device__ unsigned int g_dmin, g_dmax; // depth1 min/max as float bits (positive floats)

// ---------------- init: zero accumulators, init min/max, copy pose ----------------
__global__ void k_init(const float* __restrict__ pose_in) {
    int t = threadIdx.x;
    double* a = &g_acc[0][0];
    for (int i = t; i < 81; i += blockDim.x) a[i] = 0.0;
    if (t < 16) g_pose[t] = pose_in[t];
    if (t == 0) { g_dmin = 0x7f800000u; g_dmax = 0u; }
}

// ---------------- global min/max of depth1 ----------------
__global__ void k_minmax(const float* __restrict__ d1) {
    int i = blockIdx.x * blockDim.x + threadIdx.x;
    int stride = gridDim.x * blockDim.x;
    float mn = 3.4e38f, mx = 0.f;
    const float4* p = (const float4*)d1;
    for (int k = i; k < NPIX / 4; k += stride) {
        float4 v = p[k];
        mn = fminf(mn, fminf(fminf(v.x, v.y), fminf(v.z, v.w)));
        mx = fmaxf(mx, fmaxf(fmaxf(v.x, v.y), fmaxf(v.z, v.w)));
    }
    #pragma unroll
    for (int o = 16; o > 0; o >>= 1) {
        mn = fminf(mn, __shfl_down_sync(0xffffffffu, mn, o));
        mx = fmaxf(mx, __shfl_down_sync(0xffffffffu, mx, o));
    }
    if ((threadIdx.x & 31) == 0) {
        atomicMin(&g_dmin, __float_as_uint(mn));
        atomicMax(&g_dmax, __float_as_uint(mx));
    }
}

// ---------------- normal1 from depth1 (sobel of vertex map, cross, normalize) ----------------
__global__ void k_normal(const float* __restrict__ d1, const float* __restrict__ Km) {
    float fx = Km[0], fy = Km[4], cx = Km[2], cy = Km[5];
    float dmin = __uint_as_float(g_dmin), dmax = __uint_as_float(g_dmax);
    int idx = blockIdx.x * blockDim.x + threadIdx.x;
    if (idx >= NPIX) return;
    int r = idx / WW, c = idx % WW;

    float v[3][3][3];
    #pragma unroll
    for (int a = 0; a < 3; a++) {
        int rr = min(max(r + a - 1, 0), HH - 1);
        #pragma unroll
        for (int b = 0; b < 3; b++) {
            int cc = min(max(c + b - 1, 0), WW - 1);
            float d = d1[rr * WW + cc];
            v[a][b][0] = ((float)cc - cx) / fx * d;
            v[a][b][1] = ((float)rr - cy) / fy * d;
            v[a][b][2] = d;
        }
    }
    float dx[3], dy[3];
    #pragma unroll
    for (int k = 0; k < 3; k++) {
        dx[k] = (v[0][2][k] - v[0][0][k]) + 2.f * (v[1][2][k] - v[1][0][k]) + (v[2][2][k] - v[2][0][k]);
        dy[k] = (v[2][0][k] - v[0][0][k]) + 2.f * (v[2][1][k] - v[0][1][k]) + (v[2][2][k] - v[0][2][k]);
    }
    float nx = dx[1] * dy[2] - dx[2] * dy[1];
    float ny = dx[2] * dy[0] - dx[0] * dy[2];
    float nz = dx[0] * dy[1] - dx[1] * dy[0];
    float nrm = sqrtf(nx * nx + ny * ny + nz * nz) + 1e-8f;
    nx /= nrm; ny /= nrm; nz /= nrm;
    float dctr = v[1][1][2];
    if (dctr <= dmin || dctr >= dmax) { nx = 0.f; ny = 0.f; nz = 0.f; }
    g_nrm1[idx] = make_float4(nx, ny, nz, dctr);
}

// ---------------- fused ICP + RGB Gauss-Newton accumulation ----------------
__global__ void __launch_bounds__(256, 2)
k_accum(const float* __restrict__ d0, const float* __restrict__ x0,
        const float* __restrict__ x1, const float* __restrict__ Km, int iter) {
    float fx = Km[0], fy = Km[4], cx = Km[2], cy = Km[5];
    float p00 = g_pose[0],  p01 = g_pose[1],  p02 = g_pose[2],  p03 = g_pose[3];
    float p10 = g_pose[4],  p11 = g_pose[5],  p12 = g_pose[6],  p13 = g_pose[7];
    float p20 = g_pose[8],  p21 = g_pose[9],  p22 = g_pose[10], p23 = g_pose[11];

    float acc[27];
    #pragma unroll
    for (int i = 0; i < 27; i++) acc[i] = 0.f;

    int stride = gridDim.x * blockDim.x;
    for (int idx = blockIdx.x * blockDim.x + threadIdx.x; idx < NPIX; idx += stride) {
        int r = idx / WW, c = idx - r * WW;
        float d0v = d0[idx];
        if (!(d0v > 0.f)) continue;
        float dirx = ((float)c - cx) / fx;
        float diry = ((float)r - cy) / fy;
        float vx = dirx * d0v, vy = diry * d0v, vz = d0v;
        float tx = p00 * vx + p01 * vy + p02 * vz + p03;
        float ty = p10 * vx + p11 * vy + p12 * vz + p13;
        float tz = p20 * vx + p21 * vy + p22 * vz + p23;
        float uu = tx / tz * fx + cx;
        float vv = ty / tz * fy + cy;
        bool inview = (uu > 0.f) && (uu < (float)(WW - 1)) && (vv > 0.f) && (vv < (float)(HH - 1)) && (tz > 0.f);
        if (!inview) continue;

        float u0f = floorf(uu), v0f = floorf(vv);
        float wu = uu - u0f, wv = vv - v0f;
        int u0 = (int)u0f, v0 = (int)v0f;
        int u1 = min(u0 + 1, WW - 1), v1 = min(v0 + 1, HH - 1);
        float w00 = (1.f - wu) * (1.f - wv), w01 = wu * (1.f - wv);
        float w10 = (1.f - wu) * wv,        w11 = wu * wv;

        // ---- ICP term ----
        float4 n00 = g_nrm1[v0 * WW + u0], n01 = g_nrm1[v0 * WW + u1];
        float4 n10 = g_nrm1[v1 * WW + u0], n11 = g_nrm1[v1 * WW + u1];
        float nwx = w00 * n00.x + w01 * n01.x + w10 * n10.x + w11 * n11.x;
        float nwy = w00 * n00.y + w01 * n01.y + w10 * n10.y + w11 * n11.y;
        float nwz = w00 * n00.z + w01 * n01.z + w10 * n10.z + w11 * n11.z;
        float s0 = w00 * n00.w + w10 * n10.w;  // col u0 weighted depth
        float s1 = w01 * n01.w + w11 * n11.w;  // col u1
        float t0 = w00 * n00.w + w01 * n01.w;  // row v0
        float t1 = w10 * n10.w + w11 * n11.w;  // row v1
        float v1z = s0 + s1;
        float v1x = (s0 * ((float)u0 - cx) + s1 * ((float)u1 - cx)) / fx;
        float v1y = (t0 * ((float)v0 - cy) + t1 * ((float)v1 - cy)) / fy;
        float dfx = tx - v1x, dfy = ty - v1y, dfz = tz - v1z;
        float dist2 = dfx * dfx + dfy * dfy + dfz * dfz;
        if (v1z > 0.f && dist2 < 0.01f) {
            float res = nwx * dfx + nwy * dfy + nwz * dfz;
            float J[6];
            J[0] = ty * nwz - tz * nwy;
            J[1] = tz * nwx - tx * nwz;
            J[2] = tx * nwy - ty * nwx;
            J[3] = nwx; J[4] = nwy; J[5] = nwz;
            float ax = fabsf(res);
            float rho = (ax <= HUBER_Bf) ? ax * ax : 2.f * HUBER_Bf * ax - HUBER_Bf * HUBER_Bf;
            float xs = (ax < 1e-8f) ? 1.f : ax;
            float w = sqrtf(rho + 1e-16f) / xs;
            float w2 = w * w;
            int o = 0;
            #pragma unroll
            for (int i = 0; i < 6; i++) {
                float wi = w2 * J[i];
                #pragma unroll
                for (int j = i; j < 6; j++) acc[o++] += wi * J[j];
            }
            #pragma unroll
            for (int i = 0; i < 6; i++) acc[21 + i] += w2 * J[i] * res;
        }

        // ---- RGB term (valid: inview & mask0, both hold here) ----
        int b00 = (v0 * WW + u0) * 3, b01 = (v0 * WW + u1) * 3;
        int b10 = (v1 * WW + u0) * 3, b11 = (v1 * WW + u1) * 3;
        float resc[3];
        #pragma unroll
        for (int ch = 0; ch < 3; ch++) {
            resc[ch] = w00 * x1[b00 + ch] + w01 * x1[b01 + ch]
                     + w10 * x1[b10 + ch] + w11 * x1[b11 + ch]
                     - x0[idx * 3 + ch];
        }
        int rm = max(r - 1, 0) * WW, rp = min(r + 1, HH - 1) * WW, rw = r * WW;
        int cm = max(c - 1, 0), cp = min(c + 1, WW - 1);
        float gxv[3], gyv[3];
        #pragma unroll
        for (int ch = 0; ch < 3; ch++) {
            float a00 = x0[(rm + cm) * 3 + ch], a01 = x0[(rm + c) * 3 + ch], a02 = x0[(rm + cp) * 3 + ch];
            float a10 = x0[(rw + cm) * 3 + ch],                               a12 = x0[(rw + cp) * 3 + ch];
            float a20 = x0[(rp + cm) * 3 + ch], a21 = x0[(rp + c) * 3 + ch], a22 = x0[(rp + cp) * 3 + ch];
            float sdx = (a02 - a00) + 2.f * (a12 - a10) + (a22 - a20);
            float sdy = (a20 - a00) + 2.f * (a21 - a01) + (a22 - a02);
            float mag = sqrtf(sdx * sdx + sdy * sdy + 1e-8f);
            gxv[ch] = sdx / mag;
            gyv[ch] = sdy / mag;
        }
        float invD = 1.f / d0v;
        float Jx[6], Jy[6];
        Jx[0] = -dirx * diry * fx;        Jy[0] = -(1.f + diry * diry) * fy;
        Jx[1] = (1.f + dirx * dirx) * fx; Jy[1] = dirx * diry * fy;
        Jx[2] = -diry * fx;               Jy[2] = dirx * fy;
        Jx[3] = invD * fx;                Jy[3] = 0.f;
        Jx[4] = 0.f;                      Jy[4] = invD * fy;
        Jx[5] = -dirx * invD * fx;        Jy[5] = -diry * invD * fy;
        #pragma unroll
        for (int ch = 0; ch < 3; ch++) {
            float Jr[6];
            #pragma unroll
            for (int k = 0; k < 6; k++) Jr[k] = gxv[ch] * Jx[k] + gyv[ch] * Jy[k];
            int o = 0;
            #pragma unroll
            for (int i = 0; i < 6; i++) {
                float wi = L_RGBf * Jr[i];
                #pragma unroll
                for (int j = i; j < 6; j++) acc[o++] += wi * Jr[j];
            }
            #pragma unroll
            for (int i = 0; i < 6; i++) acc[21 + i] += L_RGBf * Jr[i] * resc[ch];
        }
    }

    // ---- block reduction -> fp64 atomics ----
    __shared__ float sred[27][9];
    int lane = threadIdx.x & 31, wid = threadIdx.x >> 5;
    #pragma unroll
    for (int i = 0; i < 27; i++) {
        float v = acc[i];
        #pragma unroll
        for (int o = 16; o > 0; o >>= 1) v += __shfl_down_sync(0xffffffffu, v, o);
        if (lane == 0) sred[i][wid] = v;
    }
    __syncthreads();
    if (threadIdx.x < 27) {
        float s = 0.f;
        #pragma unroll
        for (int w = 0; w < 8; w++) s += sred[threadIdx.x][w];
        atomicAdd(&g_acc[iter][threadIdx.x], (double)s);
    }
}

// ---------------- 6x6 solve + SE(3) pose update (single thread, fp64) ----------------
__global__ void k_solve(int iter, float* __restrict__ outp) {
    if (threadIdx.x != 0 || blockIdx.x != 0) return;
    const double* ac = g_acc[iter];
    double M[6][7];
    int o = 0;
    for (int i = 0; i < 6; i++)
        for (int j = i; j < 6; j++) { M[i][j] = ac[o]; M[j][i] = ac[o]; o++; }
    for (int i = 0; i < 6; i++) M[i][6] = ac[21 + i];
    double tr = 0.0;
    for (int i = 0; i < 6; i++) tr += M[i][i];
    for (int i = 0; i < 6; i++) M[i][i] += tr * DAMPINGd;

    // Gaussian elimination with partial pivoting
    for (int k = 0; k < 6; k++) {
        int piv = k; double mx = fabs(M[k][k]);
        for (int i = k + 1; i < 6; i++) {
            double a = fabs(M[i][k]);
            if (a > mx) { mx = a; piv = i; }
        }
        if (piv != k)
            for (int j = k; j < 7; j++) { double t = M[k][j]; M[k][j] = M[piv][j]; M[piv][j] = t; }
        double d = M[k][k];
        for (int i = k + 1; i < 6; i++) {
            double f = M[i][k] / d;
            for (int j = k; j < 7; j++) M[i][j] -= f * M[k][j];
        }
    }
    double xi[6];
    for (int i = 5; i >= 0; i--) {
        double s = M[i][6];
        for (int j = i + 1; j < 6; j++) s -= M[i][j] * xi[j];
        xi[i] = s / M[i][i];
    }

    // dR = exp_so3(-xi[:3])
    double w0 = -xi[0], w1 = -xi[1], w2 = -xi[2];
    double th2 = w0 * w0 + w1 * w1 + w2 * w2;
    if (th2 < 1e-30) th2 = 1e-30;
    double th = sqrt(th2);
    double dR[3][3] = {{1,0,0},{0,1,0},{0,0,1}};
    if (th > 1e-10) {
        double A = sin(th) / th;
        double B = (1.0 - cos(th)) / th2;
        double Wm[3][3] = {{0, -w2, w1}, {w2, 0, -w0}, {-w1, w0, 0}};
        double W2[3][3];
        for (int i = 0; i < 3; i++)
            for (int j = 0; j < 3; j++) {
                double s = 0;
                for (int k = 0; k < 3; k++) s += Wm[i][k] * Wm[k][j];
                W2[i][j] = s;
            }
        for (int i = 0; i < 3; i++)
            for (int j = 0; j < 3; j++)
                dR[i][j] = (i == j ? 1.0 : 0.0) + A * Wm[i][j] + B * W2[i][j];
    }
    double dt[3];
    for (int i = 0; i < 3; i++)
        dt[i] = -(dR[i][0] * xi[3] + dR[i][1] * xi[4] + dR[i][2] * xi[5]);

    double R0[3][3], t0[3];
    for (int i = 0; i < 3; i++) {
        for (int j = 0; j < 3; j++) R0[i][j] = (double)g_pose[i * 4 + j];
        t0[i] = (double)g_pose[i * 4 + 3];
    }
    double R1[3][3], t1[3];
    for (int i = 0; i < 3; i++) {
        for (int j = 0; j < 3; j++) {
            double s = 0;
            for (int k = 0; k < 3; k++) s += dR[i][k] * R0[k][j];
            R1[i][j] = s;
        }
        t1[i] = dR[i][0] * t0[0] + dR[i][1] * t0[1] + dR[i][2] * t0[2] + dt[i];
    }
    for (int i = 0; i < 3; i++) {
        for (int j = 0; j < 3; j++) g_pose[i * 4 + j] = (float)R1[i][j];
        g_pose[i * 4 + 3] = (float)t1[i];
    }
    // bottom row of g_pose untouched (copied from input = 0,0,0,1)
    for (int i = 0; i < 16; i++) outp[i] = g_pose[i];
}

// ---------------- launch ----------------
extern "C" void kernel_launch(void* const* d_in, const int* in_sizes, int n_in,
                              void* d_out, int out_size) {
    const float* pose10 = (const float*)d_in[0];
    const float* depth0 = (const float*)d_in[1];
    const float* depth1 = (const float*)d_in[2];
    const float* x0     = (const float*)d_in[3];
    const float* x1     = (const float*)d_in[4];
    const float* Km     = (const float*)d_in[5];
    float* out = (float*)d_out;

    k_init<<<1, 128>>>(pose10);
    k_minmax<<<512, 256>>>(depth1);
    k_normal<<<(NPIX + 255) / 256, 256>>>(depth1, Km);
    for (int it = 0; it < 3; it++) {
        k_accum<<<1200, 256>>>(depth0, x0, x1, Km, it);
        k_solve<<<1, 32>>>(it, out);
    }
}